// round 10
// baseline (speedup 1.0000x reference)
#include <cuda_runtime.h>
#include <cuda_fp16.h>
#include <math.h>
#include <stdint.h>

#define BATCH  2
#define SEQ    2048
#define DMODEL 2048
#define NHEAD  16
#define DKH    128
#define MTOT   (BATCH*SEQ)

// Scratch (device globals). Q/K: [b][h][s][64 words] fragment-permuted halves.
// V: [b][h][d][2048 key-slots] halves, key-permuted in 16-blocks. AO: fp32.
__device__ __half g_Qh[(size_t)BATCH*NHEAD*SEQ*DKH];
__device__ __half g_Ql[(size_t)BATCH*NHEAD*SEQ*DKH];
__device__ __half g_Kh[(size_t)BATCH*NHEAD*SEQ*DKH];
__device__ __half g_Vh[(size_t)BATCH*NHEAD*DKH*SEQ];
__device__ float  g_AO[(size_t)MTOT*DMODEL];

__device__ __forceinline__ int perm8(int r) { return ((r & 3) << 1) | (r >> 2); }
__device__ __forceinline__ uint32_t packh2(float a, float b) {
    __half2 h = __floats2half2_rn(a, b);
    return *reinterpret_cast<uint32_t*>(&h);
}
__device__ __forceinline__ uint32_t pack2h(__half a, __half b) {
    __half2 h = __halves2half2(a, b);
    return *reinterpret_cast<uint32_t*>(&h);
}
__device__ __forceinline__ void split2(float x, float y, uint32_t& hi, uint32_t& lo) {
    __half hx = __float2half_rn(x), hy = __float2half_rn(y);
    hi = pack2h(hx, hy);
    lo = packh2(x - __half2float(hx), y - __half2float(hy));
}
__device__ __forceinline__ void mma_f16(float* d, const uint32_t* a, const uint32_t* b) {
    asm volatile(
        "mma.sync.aligned.m16n8k16.row.col.f32.f16.f16.f32 "
        "{%0,%1,%2,%3}, {%4,%5,%6,%7}, {%8,%9}, {%0,%1,%2,%3};\n"
        : "+f"(d[0]), "+f"(d[1]), "+f"(d[2]), "+f"(d[3])
        : "r"(a[0]), "r"(a[1]), "r"(a[2]), "r"(a[3]), "r"(b[0]), "r"(b[1]));
}
__device__ __forceinline__ void cpasync16(uint32_t s, const void* g) {
    asm volatile("cp.async.cg.shared.global [%0], [%1], 16;\n" :: "r"(s), "l"(g));
}

// ---------------------------------------------------------------------------
// fp16 2-term asymmetric-split GEMM: C[m,e] = sum_d A[m,d]*W[e,d].
// A kept exact (hi+lo fp16 split), W rounded once -> Ah*Wh + Al*Wh.
// Tensor work identical to the TF32 version; only W carries rounding error.
// MODE 1: Q out (RoPE, hi+lo)  MODE 3: K out (RoPE, hi)
// MODE 0: V out (transposed)   MODE 2: fp32 out (O-projection)
// ---------------------------------------------------------------------------
#define GW 24

template<int MODE>
__global__ void __launch_bounds__(256)
gemm_f16(const float* __restrict__ A, const float* __restrict__ W,
         const int* __restrict__ pos, float* __restrict__ outF,
         __half* __restrict__ outH, __half* __restrict__ outL)
{
    __shared__ uint32_t Ah[128*GW], Al[128*GW], Wh[128*GW];

    const int bm = blockIdx.y * 128, bn = blockIdx.x * 128;
    const int tid = threadIdx.x, warp = tid >> 5, lane = tid & 31;
    const int wm = (warp & 1) * 64, wn = (warp >> 1) * 32;
    const int grp = lane >> 2, tg = lane & 3;
    const int lr = tid >> 3, lc = (tid & 7) * 4;
    const int blk = lc >> 4, wr = (lc & 15) >> 1;
    const int q0w = blk*8 + perm8(wr), q1w = blk*8 + perm8(wr + 1);

    float acc[4][4][4];
    #pragma unroll
    for (int mi = 0; mi < 4; mi++)
        #pragma unroll
        for (int ni = 0; ni < 4; ni++)
            #pragma unroll
            for (int r = 0; r < 4; r++) acc[mi][ni][r] = 0.f;

    float4 pa[4], pw[4];
    #pragma unroll
    for (int p = 0; p < 4; p++) {
        pa[p] = *(const float4*)(A + (size_t)(bm + lr + p*32)*DMODEL + lc);
        pw[p] = *(const float4*)(W + (size_t)(bn + lr + p*32)*DMODEL + lc);
    }

    for (int k0 = 0; k0 < DMODEL; k0 += 32) {
        __syncthreads();
        #pragma unroll
        for (int p = 0; p < 4; p++) {
            const int row = lr + p*32;
            uint32_t h0, l0, h1, l1;
            split2(pa[p].x, pa[p].y, h0, l0); split2(pa[p].z, pa[p].w, h1, l1);
            Ah[row*GW + q0w] = h0; Ah[row*GW + q1w] = h1;
            Al[row*GW + q0w] = l0; Al[row*GW + q1w] = l1;
            Wh[row*GW + q0w] = packh2(pw[p].x, pw[p].y);
            Wh[row*GW + q1w] = packh2(pw[p].z, pw[p].w);
        }
        __syncthreads();

        if (k0 + 32 < DMODEL) {
            #pragma unroll
            for (int p = 0; p < 4; p++) {
                pa[p] = *(const float4*)(A + (size_t)(bm + lr + p*32)*DMODEL + lc + k0 + 32);
                pw[p] = *(const float4*)(W + (size_t)(bn + lr + p*32)*DMODEL + lc + k0 + 32);
            }
        }

        #pragma unroll
        for (int s = 0; s < 2; s++) {
            uint32_t afh[4][4], afl[4][4], bfh[4][2];
            #pragma unroll
            for (int mi = 0; mi < 4; mi++) {
                const int m0 = wm + mi*16 + grp;
                uint2 t0 = *(const uint2*)&Ah[m0*GW + s*8 + 2*tg];
                uint2 t1 = *(const uint2*)&Ah[(m0+8)*GW + s*8 + 2*tg];
                afh[mi][0]=t0.x; afh[mi][1]=t1.x; afh[mi][2]=t0.y; afh[mi][3]=t1.y;
                uint2 u0 = *(const uint2*)&Al[m0*GW + s*8 + 2*tg];
                uint2 u1 = *(const uint2*)&Al[(m0+8)*GW + s*8 + 2*tg];
                afl[mi][0]=u0.x; afl[mi][1]=u1.x; afl[mi][2]=u0.y; afl[mi][3]=u1.y;
            }
            #pragma unroll
            for (int ni = 0; ni < 4; ni++) {
                const int n0 = wn + ni*8 + grp;
                uint2 b0 = *(const uint2*)&Wh[n0*GW + s*8 + 2*tg];
                bfh[ni][0] = b0.x; bfh[ni][1] = b0.y;
            }
            #pragma unroll
            for (int mi = 0; mi < 4; mi++)
                #pragma unroll
                for (int ni = 0; ni < 4; ni++) {
                    mma_f16(acc[mi][ni], afh[mi], bfh[ni]);
                    mma_f16(acc[mi][ni], afl[mi], bfh[ni]);
                }
        }
    }

    // epilogue
    float freq[4];
    if (MODE == 1 || MODE == 3) {
        #pragma unroll
        for (int ni = 0; ni < 4; ni++) {
            const int jh = (wn + ni*8 + 2*tg) & 127;
            freq[ni] = (float)exp(-(double)jh * (9.210340371976184 / 128.0));
        }
    }
    #pragma unroll
    for (int mi = 0; mi < 4; mi++) {
        #pragma unroll
        for (int hf = 0; hf < 2; hf++) {
            const int gm = bm + wm + mi*16 + grp + hf*8;
            if (MODE == 2) {
                #pragma unroll
                for (int ni = 0; ni < 4; ni++) {
                    const int col = bn + wn + ni*8 + 2*tg;
                    *(float2*)(outF + (size_t)gm*DMODEL + col)
                        = make_float2(acc[mi][ni][hf*2], acc[mi][ni][hf*2+1]);
                }
            } else {
                const int bb = gm >> 11, ss = gm & (SEQ-1);
                float p = 0.f;
                if (MODE == 1 || MODE == 3) p = (float)pos[gm];
                #pragma unroll
                for (int ni = 0; ni < 4; ni++) {
                    const int col = bn + wn + ni*8 + 2*tg;
                    const int hh = col >> 7, jh = col & 127;
                    float e = acc[mi][ni][hf*2], o = acc[mi][ni][hf*2+1];
                    if (MODE == 1 || MODE == 3) {
                        float sn, cs;
                        sincosf(p * freq[ni], &sn, &cs);
                        const float te = e*cs - o*sn;
                        o = e*sn + o*cs; e = te;
                    }
                    if (MODE == 0) {
                        const int slot = (ss & ~15) + 2*perm8((ss & 15) >> 1) + (ss & 1);
                        __half* vb = outH + ((size_t)(bb*NHEAD + hh)*DKH + jh)*SEQ;
                        vb[slot] = __float2half_rn(e);
                        vb[SEQ + slot] = __float2half_rn(o);
                    } else {
                        const size_t rowq = (size_t)(bb*NHEAD + hh)*SEQ + ss;
                        const int wp = ((jh >> 4) << 3) + perm8((jh & 15) >> 1);
                        const __half he = __float2half_rn(e), ho = __float2half_rn(o);
                        ((uint32_t*)outH)[rowq*64 + wp] = pack2h(he, ho);
                        if (MODE == 1)
                            ((uint32_t*)outL)[rowq*64 + wp]
                                = packh2(e - __half2float(he), o - __half2float(ho));
                    }
                }
            }
        }
    }
}

// ---------------------------------------------------------------------------
// fp16 causal flash attention (unchanged from R8 passing kernel).
// Q,P exact hi+lo; K,V rounded once. cp.async double-buffered K/V tiles.
// ---------------------------------------------------------------------------
#define KB (64*72)
#define VB (128*40)
#define PB (64*40)

__global__ void __launch_bounds__(128)
attn_f16(const uint32_t* __restrict__ Qh, const uint32_t* __restrict__ Ql,
         const uint32_t* __restrict__ Kh, const uint32_t* __restrict__ Vh,
         float* __restrict__ Out)
{
    extern __shared__ uint32_t smw[];
    uint32_t* PSh = smw + 2*KB + 2*VB;
    uint32_t* PSl = PSh + PB;

    const int qt = blockIdx.x, h = blockIdx.y, b = blockIdx.z;
    const int q0 = qt * 64;
    const int tid = threadIdx.x, w = tid >> 5, lane = tid & 31;
    const int grp = lane >> 2, tg = lane & 3;
    const int bh = b*NHEAD + h;
    const uint32_t sbase = (uint32_t)__cvta_generic_to_shared(smw);

    auto issue = [&](int kt, int buf) {
        const uint32_t kd = sbase + (uint32_t)buf*KB*4;
        const uint32_t vd = sbase + (2*KB + (uint32_t)buf*VB)*4;
        const uint32_t* ks = Kh + ((size_t)bh*SEQ + kt*64)*64;
        const uint32_t* vs = Vh + (size_t)bh*DKH*(SEQ/2) + kt*32;
        #pragma unroll
        for (int c = 0; c < 8; c++) {
            const int ch = tid + c*128;
            const int key = ch >> 4, cw = (ch & 15)*4;
            cpasync16(kd + (uint32_t)(key*72 + cw)*4, ks + (size_t)key*64 + cw);
        }
        #pragma unroll
        for (int c = 0; c < 8; c++) {
            const int ch = tid + c*128;
            const int d = ch >> 3, cw = (ch & 7)*4;
            cpasync16(vd + (uint32_t)(d*40 + cw)*4, vs + (size_t)d*(SEQ/2) + cw);
        }
    };

    issue(0, 0);
    asm volatile("cp.async.commit_group;\n");

    // Q fragments (exact hi+lo), LDG overlapped with tile-0 copy
    const int mlo = q0 + w*16 + grp;
    uint32_t qah[8][4], qal[8][4];
    {
        const uint32_t* qh = Qh + ((size_t)bh*SEQ + mlo)*64;
        const uint32_t* ql = Ql + ((size_t)bh*SEQ + mlo)*64;
        #pragma unroll
        for (int s = 0; s < 8; s++) {
            uint2 t0 = *(const uint2*)&qh[s*8 + 2*tg];
            uint2 t1 = *(const uint2*)&qh[512 + s*8 + 2*tg];
            qah[s][0]=t0.x; qah[s][1]=t1.x; qah[s][2]=t0.y; qah[s][3]=t1.y;
            uint2 u0 = *(const uint2*)&ql[s*8 + 2*tg];
            uint2 u1 = *(const uint2*)&ql[512 + s*8 + 2*tg];
            qal[s][0]=u0.x; qal[s][1]=u1.x; qal[s][2]=u0.y; qal[s][3]=u1.y;
        }
    }

    float oacc[16][4];
    #pragma unroll
    for (int ni = 0; ni < 16; ni++)
        #pragma unroll
        for (int r = 0; r < 4; r++) oacc[ni][r] = 0.f;

    float m_lo = -1e30f, m_hi = -1e30f, l_lo = 0.f, l_hi = 0.f;
    const float scale = 0.08838834764831845f;
    const int prow_lo = (w*16 + grp)*40, prow_hi = prow_lo + 8*40;

    for (int kt = 0; kt <= qt; kt++) {
        const int buf = kt & 1, k0 = kt*64;
        __syncthreads();
        if (kt < qt) {
            issue(kt+1, buf^1);
            asm volatile("cp.async.commit_group;\n");
            asm volatile("cp.async.wait_group 1;\n");
        } else {
            asm volatile("cp.async.wait_group 0;\n");
        }
        __syncthreads();
        const uint32_t* KS = smw + buf*KB;
        const uint32_t* VS = smw + 2*KB + buf*VB;

        // S = Q K^T
        float sacc[8][4];
        #pragma unroll
        for (int ni = 0; ni < 8; ni++)
            #pragma unroll
            for (int r = 0; r < 4; r++) sacc[ni][r] = 0.f;
        #pragma unroll
        for (int s = 0; s < 8; s++) {
            #pragma unroll
            for (int ni = 0; ni < 8; ni++) {
                uint2 bk = *(const uint2*)&KS[(ni*8 + grp)*72 + s*8 + 2*tg];
                uint32_t bv[2] = { bk.x, bk.y };
                mma_f16(sacc[ni], qah[s], bv);
                mma_f16(sacc[ni], qal[s], bv);
            }
        }

        // online softmax (fp32)
        const bool diag = (kt == qt);
        float mloc_lo = -1e30f, mloc_hi = -1e30f;
        #pragma unroll
        for (int ni = 0; ni < 8; ni++) {
            const int col = k0 + ni*8 + 2*tg;
            float s0 = sacc[ni][0]*scale, s1 = sacc[ni][1]*scale;
            float s2 = sacc[ni][2]*scale, s3 = sacc[ni][3]*scale;
            if (diag) {
                if (col     > mlo    ) s0 = -1e30f;
                if (col + 1 > mlo    ) s1 = -1e30f;
                if (col     > mlo + 8) s2 = -1e30f;
                if (col + 1 > mlo + 8) s3 = -1e30f;
            }
            sacc[ni][0]=s0; sacc[ni][1]=s1; sacc[ni][2]=s2; sacc[ni][3]=s3;
            mloc_lo = fmaxf(mloc_lo, fmaxf(s0, s1));
            mloc_hi = fmaxf(mloc_hi, fmaxf(s2, s3));
        }
        mloc_lo = fmaxf(mloc_lo, __shfl_xor_sync(0xffffffffu, mloc_lo, 1));
        mloc_lo = fmaxf(mloc_lo, __shfl_xor_sync(0xffffffffu, mloc_lo, 2));
        mloc_hi = fmaxf(mloc_hi, __shfl_xor_sync(0xffffffffu, mloc_hi, 1));
        mloc_hi = fmaxf(mloc_hi, __shfl_xor_sync(0xffffffffu, mloc_hi, 2));
        const float mn_lo = fmaxf(m_lo, mloc_lo), mn_hi = fmaxf(m_hi, mloc_hi);
        const float corr_lo = __expf(m_lo - mn_lo), corr_hi = __expf(m_hi - mn_hi);

        float ls_lo = 0.f, ls_hi = 0.f;
        #pragma unroll
        for (int ni = 0; ni < 8; ni++) {
            const float p0 = __expf(sacc[ni][0] - mn_lo);
            const float p1 = __expf(sacc[ni][1] - mn_lo);
            const float p2 = __expf(sacc[ni][2] - mn_hi);
            const float p3 = __expf(sacc[ni][3] - mn_hi);
            ls_lo += p0 + p1;  ls_hi += p2 + p3;
            const int kwi = ni*4 + tg;
            const int pp = ((kwi >> 3) << 3) + perm8(kwi & 7);
            uint32_t hi, lo;
            split2(p0, p1, hi, lo);
            PSh[prow_lo + pp] = hi;  PSl[prow_lo + pp] = lo;
            split2(p2, p3, hi, lo);
            PSh[prow_hi + pp] = hi;  PSl[prow_hi + pp] = lo;
        }
        l_lo = l_lo*corr_lo + ls_lo;  m_lo = mn_lo;
        l_hi = l_hi*corr_hi + ls_hi;  m_hi = mn_hi;
        #pragma unroll
        for (int ni = 0; ni < 16; ni++) {
            oacc[ni][0] *= corr_lo; oacc[ni][1] *= corr_lo;
            oacc[ni][2] *= corr_hi; oacc[ni][3] *= corr_hi;
        }
        __syncwarp();

        // O += P V
        #pragma unroll
        for (int kk = 0; kk < 4; kk++) {
            uint2 plh = *(const uint2*)&PSh[prow_lo + kk*8 + 2*tg];
            uint2 phh = *(const uint2*)&PSh[prow_hi + kk*8 + 2*tg];
            uint32_t pah[4] = { plh.x, phh.x, plh.y, phh.y };
            uint2 pll = *(const uint2*)&PSl[prow_lo + kk*8 + 2*tg];
            uint2 phl = *(const uint2*)&PSl[prow_hi + kk*8 + 2*tg];
            uint32_t pal[4] = { pll.x, phl.x, pll.y, phl.y };
            #pragma unroll
            for (int ni = 0; ni < 16; ni++) {
                uint2 bv2 = *(const uint2*)&VS[(ni*8 + grp)*40 + kk*8 + 2*tg];
                uint32_t bv[2] = { bv2.x, bv2.y };
                mma_f16(oacc[ni], pah, bv);
                mma_f16(oacc[ni], pal, bv);
            }
        }
    }

    // epilogue
    l_lo += __shfl_xor_sync(0xffffffffu, l_lo, 1);
    l_lo += __shfl_xor_sync(0xffffffffu, l_lo, 2);
    l_hi += __shfl_xor_sync(0xffffffffu, l_hi, 1);
    l_hi += __shfl_xor_sync(0xffffffffu, l_hi, 2);
    const float iv_lo = 1.f / l_lo, iv_hi = 1.f / l_hi;
    float* olo = Out + ((size_t)(b*SEQ + mlo))*DMODEL + h*DKH;
    float* ohi = olo + (size_t)8*DMODEL;
    #pragma unroll
    for (int ni = 0; ni < 16; ni++) {
        *(float2*)(olo + ni*8 + 2*tg) = make_float2(oacc[ni][0]*iv_lo, oacc[ni][1]*iv_lo);
        *(float2*)(ohi + ni*8 + 2*tg) = make_float2(oacc[ni][2]*iv_hi, oacc[ni][3]*iv_hi);
    }
}

// ---------------------------------------------------------------------------
extern "C" void kernel_launch(void* const* d_in, const int* in_sizes, int n_in,
                              void* d_out, int out_size)
{
    (void)in_sizes; (void)n_in; (void)out_size;
    const float* x  = (const float*)d_in[0];
    const int*   tp = (const int*)  d_in[1];
    const float* wq = (const float*)d_in[2];
    const float* wk = (const float*)d_in[3];
    const float* wv = (const float*)d_in[4];
    const float* wo = (const float*)d_in[5];
    float* out = (float*)d_out;

    __half *Qh, *Ql, *Kh, *Vh; float* AO;
    cudaGetSymbolAddress((void**)&Qh, g_Qh);
    cudaGetSymbolAddress((void**)&Ql, g_Ql);
    cudaGetSymbolAddress((void**)&Kh, g_Kh);
    cudaGetSymbolAddress((void**)&Vh, g_Vh);
    cudaGetSymbolAddress((void**)&AO, g_AO);

    const dim3 gg(DMODEL/128, MTOT/128);
    gemm_f16<1><<<gg, 256>>>(x, wq, tp, nullptr, Qh, Ql);
    gemm_f16<3><<<gg, 256>>>(x, wk, tp, nullptr, Kh, nullptr);
    gemm_f16<0><<<gg, 256>>>(x, wv, tp, nullptr, Vh, nullptr);

    const int smem = (2*KB + 2*VB + 2*PB) * 4;
    cudaFuncSetAttribute(attn_f16,
                         cudaFuncAttributeMaxDynamicSharedMemorySize, smem);
    attn_f16<<<dim3(SEQ/64, NHEAD, BATCH), 128, smem>>>(
        (const uint32_t*)Qh, (const uint32_t*)Ql,
        (const uint32_t*)Kh, (const uint32_t*)Vh, AO);

    gemm_f16<2><<<gg, 256>>>(AO, wo, tp, out, nullptr, nullptr);
}

// round 11
// speedup vs baseline: 1.0014x; 1.0014x over previous
#include <cuda_runtime.h>
#include <cuda_fp16.h>
#include <math.h>
#include <stdint.h>

#define BATCH  2
#define SEQ    2048
#define DMODEL 2048
#define NHEAD  16
#define DKH    128
#define MTOT   (BATCH*SEQ)

// Scratch (device globals). Q/K: [b][h][s][64 words] fragment-permuted halves.
// V: [b][h][d][2048 key-slots] halves, key-permuted in 16-blocks. AO: fp32.
__device__ __half g_Qh[(size_t)BATCH*NHEAD*SEQ*DKH];
__device__ __half g_Ql[(size_t)BATCH*NHEAD*SEQ*DKH];
__device__ __half g_Kh[(size_t)BATCH*NHEAD*SEQ*DKH];
__device__ __half g_Vh[(size_t)BATCH*NHEAD*DKH*SEQ];
__device__ float  g_AO[(size_t)MTOT*DMODEL];

__device__ __forceinline__ int perm8(int r) { return ((r & 3) << 1) | (r >> 2); }
__device__ __forceinline__ uint32_t packh2(float a, float b) {
    __half2 h = __floats2half2_rn(a, b);
    return *reinterpret_cast<uint32_t*>(&h);
}
__device__ __forceinline__ uint32_t pack2h(__half a, __half b) {
    __half2 h = __halves2half2(a, b);
    return *reinterpret_cast<uint32_t*>(&h);
}
__device__ __forceinline__ void split2(float x, float y, uint32_t& hi, uint32_t& lo) {
    __half hx = __float2half_rn(x), hy = __float2half_rn(y);
    hi = pack2h(hx, hy);
    lo = packh2(x - __half2float(hx), y - __half2float(hy));
}
__device__ __forceinline__ void mma_f16(float* d, const uint32_t* a, const uint32_t* b) {
    asm volatile(
        "mma.sync.aligned.m16n8k16.row.col.f32.f16.f16.f32 "
        "{%0,%1,%2,%3}, {%4,%5,%6,%7}, {%8,%9}, {%0,%1,%2,%3};\n"
        : "+f"(d[0]), "+f"(d[1]), "+f"(d[2]), "+f"(d[3])
        : "r"(a[0]), "r"(a[1]), "r"(a[2]), "r"(a[3]), "r"(b[0]), "r"(b[1]));
}
__device__ __forceinline__ void cpasync16(uint32_t s, const void* g) {
    asm volatile("cp.async.cg.shared.global [%0], [%1], 16;\n" :: "r"(s), "l"(g));
}

// ---------------------------------------------------------------------------
// fp16 2-term asymmetric-split GEMM: C[m,e] = sum_d A[m,d]*W[e,d].
// A kept exact (hi+lo fp16 split), W rounded once -> Ah*Wh + Al*Wh.
// Tensor work identical to the TF32 version; only W carries rounding error.
// MODE 1: Q out (RoPE, hi+lo)  MODE 3: K out (RoPE, hi)
// MODE 0: V out (transposed)   MODE 2: fp32 out (O-projection)
// ---------------------------------------------------------------------------
#define GW 24

template<int MODE>
__global__ void __launch_bounds__(256)
gemm_f16(const float* __restrict__ A, const float* __restrict__ W,
         const int* __restrict__ pos, float* __restrict__ outF,
         __half* __restrict__ outH, __half* __restrict__ outL)
{
    __shared__ uint32_t Ah[128*GW], Al[128*GW], Wh[128*GW];

    const int bm = blockIdx.y * 128, bn = blockIdx.x * 128;
    const int tid = threadIdx.x, warp = tid >> 5, lane = tid & 31;
    const int wm = (warp & 1) * 64, wn = (warp >> 1) * 32;
    const int grp = lane >> 2, tg = lane & 3;
    const int lr = tid >> 3, lc = (tid & 7) * 4;
    const int blk = lc >> 4, wr = (lc & 15) >> 1;
    const int q0w = blk*8 + perm8(wr), q1w = blk*8 + perm8(wr + 1);

    float acc[4][4][4];
    #pragma unroll
    for (int mi = 0; mi < 4; mi++)
        #pragma unroll
        for (int ni = 0; ni < 4; ni++)
            #pragma unroll
            for (int r = 0; r < 4; r++) acc[mi][ni][r] = 0.f;

    float4 pa[4], pw[4];
    #pragma unroll
    for (int p = 0; p < 4; p++) {
        pa[p] = *(const float4*)(A + (size_t)(bm + lr + p*32)*DMODEL + lc);
        pw[p] = *(const float4*)(W + (size_t)(bn + lr + p*32)*DMODEL + lc);
    }

    for (int k0 = 0; k0 < DMODEL; k0 += 32) {
        __syncthreads();
        #pragma unroll
        for (int p = 0; p < 4; p++) {
            const int row = lr + p*32;
            uint32_t h0, l0, h1, l1;
            split2(pa[p].x, pa[p].y, h0, l0); split2(pa[p].z, pa[p].w, h1, l1);
            Ah[row*GW + q0w] = h0; Ah[row*GW + q1w] = h1;
            Al[row*GW + q0w] = l0; Al[row*GW + q1w] = l1;
            Wh[row*GW + q0w] = packh2(pw[p].x, pw[p].y);
            Wh[row*GW + q1w] = packh2(pw[p].z, pw[p].w);
        }
        __syncthreads();

        if (k0 + 32 < DMODEL) {
            #pragma unroll
            for (int p = 0; p < 4; p++) {
                pa[p] = *(const float4*)(A + (size_t)(bm + lr + p*32)*DMODEL + lc + k0 + 32);
                pw[p] = *(const float4*)(W + (size_t)(bn + lr + p*32)*DMODEL + lc + k0 + 32);
            }
        }

        #pragma unroll
        for (int s = 0; s < 2; s++) {
            uint32_t afh[4][4], afl[4][4], bfh[4][2];
            #pragma unroll
            for (int mi = 0; mi < 4; mi++) {
                const int m0 = wm + mi*16 + grp;
                uint2 t0 = *(const uint2*)&Ah[m0*GW + s*8 + 2*tg];
                uint2 t1 = *(const uint2*)&Ah[(m0+8)*GW + s*8 + 2*tg];
                afh[mi][0]=t0.x; afh[mi][1]=t1.x; afh[mi][2]=t0.y; afh[mi][3]=t1.y;
                uint2 u0 = *(const uint2*)&Al[m0*GW + s*8 + 2*tg];
                uint2 u1 = *(const uint2*)&Al[(m0+8)*GW + s*8 + 2*tg];
                afl[mi][0]=u0.x; afl[mi][1]=u1.x; afl[mi][2]=u0.y; afl[mi][3]=u1.y;
            }
            #pragma unroll
            for (int ni = 0; ni < 4; ni++) {
                const int n0 = wn + ni*8 + grp;
                uint2 b0 = *(const uint2*)&Wh[n0*GW + s*8 + 2*tg];
                bfh[ni][0] = b0.x; bfh[ni][1] = b0.y;
            }
            #pragma unroll
            for (int mi = 0; mi < 4; mi++)
                #pragma unroll
                for (int ni = 0; ni < 4; ni++) {
                    mma_f16(acc[mi][ni], afh[mi], bfh[ni]);
                    mma_f16(acc[mi][ni], afl[mi], bfh[ni]);
                }
        }
    }

    // epilogue
    float freq[4];
    if (MODE == 1 || MODE == 3) {
        #pragma unroll
        for (int ni = 0; ni < 4; ni++) {
            const int jh = (wn + ni*8 + 2*tg) & 127;
            freq[ni] = (float)exp(-(double)jh * (9.210340371976184 / 128.0));
        }
    }
    #pragma unroll
    for (int mi = 0; mi < 4; mi++) {
        #pragma unroll
        for (int hf = 0; hf < 2; hf++) {
            const int gm = bm + wm + mi*16 + grp + hf*8;
            if (MODE == 2) {
                #pragma unroll
                for (int ni = 0; ni < 4; ni++) {
                    const int col = bn + wn + ni*8 + 2*tg;
                    *(float2*)(outF + (size_t)gm*DMODEL + col)
                        = make_float2(acc[mi][ni][hf*2], acc[mi][ni][hf*2+1]);
                }
            } else {
                const int bb = gm >> 11, ss = gm & (SEQ-1);
                float p = 0.f;
                if (MODE == 1 || MODE == 3) p = (float)pos[gm];
                #pragma unroll
                for (int ni = 0; ni < 4; ni++) {
                    const int col = bn + wn + ni*8 + 2*tg;
                    const int hh = col >> 7, jh = col & 127;
                    float e = acc[mi][ni][hf*2], o = acc[mi][ni][hf*2+1];
                    if (MODE == 1 || MODE == 3) {
                        float sn, cs;
                        sincosf(p * freq[ni], &sn, &cs);
                        const float te = e*cs - o*sn;
                        o = e*sn + o*cs; e = te;
                    }
                    if (MODE == 0) {
                        const int slot = (ss & ~15) + 2*perm8((ss & 15) >> 1) + (ss & 1);
                        __half* vb = outH + ((size_t)(bb*NHEAD + hh)*DKH + jh)*SEQ;
                        vb[slot] = __float2half_rn(e);
                        vb[SEQ + slot] = __float2half_rn(o);
                    } else {
                        const size_t rowq = (size_t)(bb*NHEAD + hh)*SEQ + ss;
                        const int wp = ((jh >> 4) << 3) + perm8((jh & 15) >> 1);
                        const __half he = __float2half_rn(e), ho = __float2half_rn(o);
                        ((uint32_t*)outH)[rowq*64 + wp] = pack2h(he, ho);
                        if (MODE == 1)
                            ((uint32_t*)outL)[rowq*64 + wp]
                                = packh2(e - __half2float(he), o - __half2float(ho));
                    }
                }
            }
        }
    }
}

// ---------------------------------------------------------------------------
// fp16 causal flash attention (unchanged from R8 passing kernel).
// Q,P exact hi+lo; K,V rounded once. cp.async double-buffered K/V tiles.
// ---------------------------------------------------------------------------
#define KB (64*72)
#define VB (128*40)
#define PB (64*40)

__global__ void __launch_bounds__(128)
attn_f16(const uint32_t* __restrict__ Qh, const uint32_t* __restrict__ Ql,
         const uint32_t* __restrict__ Kh, const uint32_t* __restrict__ Vh,
         float* __restrict__ Out)
{
    extern __shared__ uint32_t smw[];
    uint32_t* PSh = smw + 2*KB + 2*VB;
    uint32_t* PSl = PSh + PB;

    const int qt = blockIdx.x, h = blockIdx.y, b = blockIdx.z;
    const int q0 = qt * 64;
    const int tid = threadIdx.x, w = tid >> 5, lane = tid & 31;
    const int grp = lane >> 2, tg = lane & 3;
    const int bh = b*NHEAD + h;
    const uint32_t sbase = (uint32_t)__cvta_generic_to_shared(smw);

    auto issue = [&](int kt, int buf) {
        const uint32_t kd = sbase + (uint32_t)buf*KB*4;
        const uint32_t vd = sbase + (2*KB + (uint32_t)buf*VB)*4;
        const uint32_t* ks = Kh + ((size_t)bh*SEQ + kt*64)*64;
        const uint32_t* vs = Vh + (size_t)bh*DKH*(SEQ/2) + kt*32;
        #pragma unroll
        for (int c = 0; c < 8; c++) {
            const int ch = tid + c*128;
            const int key = ch >> 4, cw = (ch & 15)*4;
            cpasync16(kd + (uint32_t)(key*72 + cw)*4, ks + (size_t)key*64 + cw);
        }
        #pragma unroll
        for (int c = 0; c < 8; c++) {
            const int ch = tid + c*128;
            const int d = ch >> 3, cw = (ch & 7)*4;
            cpasync16(vd + (uint32_t)(d*40 + cw)*4, vs + (size_t)d*(SEQ/2) + cw);
        }
    };

    issue(0, 0);
    asm volatile("cp.async.commit_group;\n");

    // Q fragments (exact hi+lo), LDG overlapped with tile-0 copy
    const int mlo = q0 + w*16 + grp;
    uint32_t qah[8][4], qal[8][4];
    {
        const uint32_t* qh = Qh + ((size_t)bh*SEQ + mlo)*64;
        const uint32_t* ql = Ql + ((size_t)bh*SEQ + mlo)*64;
        #pragma unroll
        for (int s = 0; s < 8; s++) {
            uint2 t0 = *(const uint2*)&qh[s*8 + 2*tg];
            uint2 t1 = *(const uint2*)&qh[512 + s*8 + 2*tg];
            qah[s][0]=t0.x; qah[s][1]=t1.x; qah[s][2]=t0.y; qah[s][3]=t1.y;
            uint2 u0 = *(const uint2*)&ql[s*8 + 2*tg];
            uint2 u1 = *(const uint2*)&ql[512 + s*8 + 2*tg];
            qal[s][0]=u0.x; qal[s][1]=u1.x; qal[s][2]=u0.y; qal[s][3]=u1.y;
        }
    }

    float oacc[16][4];
    #pragma unroll
    for (int ni = 0; ni < 16; ni++)
        #pragma unroll
        for (int r = 0; r < 4; r++) oacc[ni][r] = 0.f;

    float m_lo = -1e30f, m_hi = -1e30f, l_lo = 0.f, l_hi = 0.f;
    const float scale = 0.08838834764831845f;
    const int prow_lo = (w*16 + grp)*40, prow_hi = prow_lo + 8*40;

    for (int kt = 0; kt <= qt; kt++) {
        const int buf = kt & 1, k0 = kt*64;
        __syncthreads();
        if (kt < qt) {
            issue(kt+1, buf^1);
            asm volatile("cp.async.commit_group;\n");
            asm volatile("cp.async.wait_group 1;\n");
        } else {
            asm volatile("cp.async.wait_group 0;\n");
        }
        __syncthreads();
        const uint32_t* KS = smw + buf*KB;
        const uint32_t* VS = smw + 2*KB + buf*VB;

        // S = Q K^T
        float sacc[8][4];
        #pragma unroll
        for (int ni = 0; ni < 8; ni++)
            #pragma unroll
            for (int r = 0; r < 4; r++) sacc[ni][r] = 0.f;
        #pragma unroll
        for (int s = 0; s < 8; s++) {
            #pragma unroll
            for (int ni = 0; ni < 8; ni++) {
                uint2 bk = *(const uint2*)&KS[(ni*8 + grp)*72 + s*8 + 2*tg];
                uint32_t bv[2] = { bk.x, bk.y };
                mma_f16(sacc[ni], qah[s], bv);
                mma_f16(sacc[ni], qal[s], bv);
            }
        }

        // online softmax (fp32)
        const bool diag = (kt == qt);
        float mloc_lo = -1e30f, mloc_hi = -1e30f;
        #pragma unroll
        for (int ni = 0; ni < 8; ni++) {
            const int col = k0 + ni*8 + 2*tg;
            float s0 = sacc[ni][0]*scale, s1 = sacc[ni][1]*scale;
            float s2 = sacc[ni][2]*scale, s3 = sacc[ni][3]*scale;
            if (diag) {
                if (col     > mlo    ) s0 = -1e30f;
                if (col + 1 > mlo    ) s1 = -1e30f;
                if (col     > mlo + 8) s2 = -1e30f;
                if (col + 1 > mlo + 8) s3 = -1e30f;
            }
            sacc[ni][0]=s0; sacc[ni][1]=s1; sacc[ni][2]=s2; sacc[ni][3]=s3;
            mloc_lo = fmaxf(mloc_lo, fmaxf(s0, s1));
            mloc_hi = fmaxf(mloc_hi, fmaxf(s2, s3));
        }
        mloc_lo = fmaxf(mloc_lo, __shfl_xor_sync(0xffffffffu, mloc_lo, 1));
        mloc_lo = fmaxf(mloc_lo, __shfl_xor_sync(0xffffffffu, mloc_lo, 2));
        mloc_hi = fmaxf(mloc_hi, __shfl_xor_sync(0xffffffffu, mloc_hi, 1));
        mloc_hi = fmaxf(mloc_hi, __shfl_xor_sync(0xffffffffu, mloc_hi, 2));
        const float mn_lo = fmaxf(m_lo, mloc_lo), mn_hi = fmaxf(m_hi, mloc_hi);
        const float corr_lo = __expf(m_lo - mn_lo), corr_hi = __expf(m_hi - mn_hi);

        float ls_lo = 0.f, ls_hi = 0.f;
        #pragma unroll
        for (int ni = 0; ni < 8; ni++) {
            const float p0 = __expf(sacc[ni][0] - mn_lo);
            const float p1 = __expf(sacc[ni][1] - mn_lo);
            const float p2 = __expf(sacc[ni][2] - mn_hi);
            const float p3 = __expf(sacc[ni][3] - mn_hi);
            ls_lo += p0 + p1;  ls_hi += p2 + p3;
            const int kwi = ni*4 + tg;
            const int pp = ((kwi >> 3) << 3) + perm8(kwi & 7);
            uint32_t hi, lo;
            split2(p0, p1, hi, lo);
            PSh[prow_lo + pp] = hi;  PSl[prow_lo + pp] = lo;
            split2(p2, p3, hi, lo);
            PSh[prow_hi + pp] = hi;  PSl[prow_hi + pp] = lo;
        }
        l_lo = l_lo*corr_lo + ls_lo;  m_lo = mn_lo;
        l_hi = l_hi*corr_hi + ls_hi;  m_hi = mn_hi;
        #pragma unroll
        for (int ni = 0; ni < 16; ni++) {
            oacc[ni][0] *= corr_lo; oacc[ni][1] *= corr_lo;
            oacc[ni][2] *= corr_hi; oacc[ni][3] *= corr_hi;
        }
        __syncwarp();

        // O += P V
        #pragma unroll
        for (int kk = 0; kk < 4; kk++) {
            uint2 plh = *(const uint2*)&PSh[prow_lo + kk*8 + 2*tg];
            uint2 phh = *(const uint2*)&PSh[prow_hi + kk*8 + 2*tg];
            uint32_t pah[4] = { plh.x, phh.x, plh.y, phh.y };
            uint2 pll = *(const uint2*)&PSl[prow_lo + kk*8 + 2*tg];
            uint2 phl = *(const uint2*)&PSl[prow_hi + kk*8 + 2*tg];
            uint32_t pal[4] = { pll.x, phl.x, pll.y, phl.y };
            #pragma unroll
            for (int ni = 0; ni < 16; ni++) {
                uint2 bv2 = *(const uint2*)&VS[(ni*8 + grp)*40 + kk*8 + 2*tg];
                uint32_t bv[2] = { bv2.x, bv2.y };
                mma_f16(oacc[ni], pah, bv);
                mma_f16(oacc[ni], pal, bv);
            }
        }
    }

    // epilogue
    l_lo += __shfl_xor_sync(0xffffffffu, l_lo, 1);
    l_lo += __shfl_xor_sync(0xffffffffu, l_lo, 2);
    l_hi += __shfl_xor_sync(0xffffffffu, l_hi, 1);
    l_hi += __shfl_xor_sync(0xffffffffu, l_hi, 2);
    const float iv_lo = 1.f / l_lo, iv_hi = 1.f / l_hi;
    float* olo = Out + ((size_t)(b*SEQ + mlo))*DMODEL + h*DKH;
    float* ohi = olo + (size_t)8*DMODEL;
    #pragma unroll
    for (int ni = 0; ni < 16; ni++) {
        *(float2*)(olo + ni*8 + 2*tg) = make_float2(oacc[ni][0]*iv_lo, oacc[ni][1]*iv_lo);
        *(float2*)(ohi + ni*8 + 2*tg) = make_float2(oacc[ni][2]*iv_hi, oacc[ni][3]*iv_hi);
    }
}

// ---------------------------------------------------------------------------
extern "C" void kernel_launch(void* const* d_in, const int* in_sizes, int n_in,
                              void* d_out, int out_size)
{
    (void)in_sizes; (void)n_in; (void)out_size;
    const float* x  = (const float*)d_in[0];
    const int*   tp = (const int*)  d_in[1];
    const float* wq = (const float*)d_in[2];
    const float* wk = (const float*)d_in[3];
    const float* wv = (const float*)d_in[4];
    const float* wo = (const float*)d_in[5];
    float* out = (float*)d_out;

    __half *Qh, *Ql, *Kh, *Vh; float* AO;
    cudaGetSymbolAddress((void**)&Qh, g_Qh);
    cudaGetSymbolAddress((void**)&Ql, g_Ql);
    cudaGetSymbolAddress((void**)&Kh, g_Kh);
    cudaGetSymbolAddress((void**)&Vh, g_Vh);
    cudaGetSymbolAddress((void**)&AO, g_AO);

    const dim3 gg(DMODEL/128, MTOT/128);
    gemm_f16<1><<<gg, 256>>>(x, wq, tp, nullptr, Qh, Ql);
    gemm_f16<3><<<gg, 256>>>(x, wk, tp, nullptr, Kh, nullptr);
    gemm_f16<0><<<gg, 256>>>(x, wv, tp, nullptr, Vh, nullptr);

    const int smem = (2*KB + 2*VB + 2*PB) * 4;
    cudaFuncSetAttribute(attn_f16,
                         cudaFuncAttributeMaxDynamicSharedMemorySize, smem);
    attn_f16<<<dim3(SEQ/64, NHEAD, BATCH), 128, smem>>>(
        (const uint32_t*)Qh, (const uint32_t*)Ql,
        (const uint32_t*)Kh, (const uint32_t*)Vh, AO);

    gemm_f16<2><<<gg, 256>>>(AO, wo, tp, out, nullptr, nullptr);
}

// round 14
// speedup vs baseline: 1.0490x; 1.0476x over previous
#include <cuda_runtime.h>
#include <cuda_fp16.h>
#include <math.h>
#include <stdint.h>

#define BATCH  2
#define SEQ    2048
#define DMODEL 2048
#define NHEAD  16
#define DKH    128
#define MTOT   (BATCH*SEQ)
#define RW     (DMODEL/2)   // 1024 words per packed row

// Packed planes: rows of 1024 uint32 words, fragment-permuted fp16 pairs.
__device__ uint32_t g_Xh[(size_t)MTOT*RW];
__device__ uint32_t g_Xl[(size_t)MTOT*RW];
__device__ uint32_t g_Wq[(size_t)DMODEL*RW];
__device__ uint32_t g_Wk[(size_t)DMODEL*RW];
__device__ uint32_t g_Wv[(size_t)DMODEL*RW];
__device__ uint32_t g_Wo[(size_t)DMODEL*RW];
__device__ uint32_t g_AOh[(size_t)MTOT*RW];
__device__ uint32_t g_AOl[(size_t)MTOT*RW];
// Attention operand layouts (as in R11).
__device__ __half g_Qh[(size_t)BATCH*NHEAD*SEQ*DKH];
__device__ __half g_Ql[(size_t)BATCH*NHEAD*SEQ*DKH];
__device__ __half g_Kh[(size_t)BATCH*NHEAD*SEQ*DKH];
__device__ __half g_Vh[(size_t)BATCH*NHEAD*DKH*SEQ];

__device__ __forceinline__ int perm8(int r) { return ((r & 3) << 1) | (r >> 2); }
__device__ __forceinline__ uint32_t packh2(float a, float b) {
    __half2 h = __floats2half2_rn(a, b);
    return *reinterpret_cast<uint32_t*>(&h);
}
__device__ __forceinline__ uint32_t pack2h(__half a, __half b) {
    __half2 h = __halves2half2(a, b);
    return *reinterpret_cast<uint32_t*>(&h);
}
__device__ __forceinline__ void split2(float x, float y, uint32_t& hi, uint32_t& lo) {
    __half hx = __float2half_rn(x), hy = __float2half_rn(y);
    hi = pack2h(hx, hy);
    lo = packh2(x - __half2float(hx), y - __half2float(hy));
}
__device__ __forceinline__ void mma_f16(float* d, const uint32_t* a, const uint32_t* b) {
    asm volatile(
        "mma.sync.aligned.m16n8k16.row.col.f32.f16.f16.f32 "
        "{%0,%1,%2,%3}, {%4,%5,%6,%7}, {%8,%9}, {%0,%1,%2,%3};\n"
        : "+f"(d[0]), "+f"(d[1]), "+f"(d[2]), "+f"(d[3])
        : "r"(a[0]), "r"(a[1]), "r"(a[2]), "r"(a[3]), "r"(b[0]), "r"(b[1]));
}
__device__ __forceinline__ void cpasync16(uint32_t s, const void* g) {
    asm volatile("cp.async.cg.shared.global [%0], [%1], 16;\n" :: "r"(s), "l"(g));
}

// ---------------------------------------------------------------------------
// Prep: fp32 rows -> packed fp16 hi(/lo) planes in fragment-word layout.
// word index within row for float pair cpair: ((cpair>>3)<<3)+perm8(cpair&7)
// ---------------------------------------------------------------------------
__global__ void __launch_bounds__(256)
pack_rows(const float* __restrict__ src, uint32_t* __restrict__ hi,
          uint32_t* __restrict__ lo, int nwords)
{
    const int idx = blockIdx.x * 256 + threadIdx.x;
    if (idx >= nwords) return;
    const int cpair = idx & (RW-1), row = idx >> 10;
    const int wp = ((cpair >> 3) << 3) + perm8(cpair & 7);
    const float2 v = ((const float2*)src)[idx];
    const __half hx = __float2half_rn(v.x), hy = __float2half_rn(v.y);
    hi[((size_t)row << 10) + wp] = pack2h(hx, hy);
    if (lo)
        lo[((size_t)row << 10) + wp]
            = packh2(v.x - __half2float(hx), v.y - __half2float(hy));
}

// ---------------------------------------------------------------------------
// Packed-input 2-term GEMM: C = A x W^T, A exact (hi+lo), W hi only.
// 4-stage cp.async pipeline, zero in-loop conversion, 1 barrier per chunk.
// MODE 1: Q out (RoPE, hi+lo)  MODE 3: K out (RoPE, hi)
// MODE 0: V out (transposed)   MODE 2: fp32 out (O-projection)
// ---------------------------------------------------------------------------
#define SROW  24
#define PLANE (128*SROW)
#define STGW  (3*PLANE)
#define NKCH  (DMODEL/32)

template<int MODE>
__global__ void __launch_bounds__(256)
gemm_pk(const uint32_t* __restrict__ Agh, const uint32_t* __restrict__ Agl,
        const uint32_t* __restrict__ Wgh, const int* __restrict__ pos,
        float* __restrict__ outF, __half* __restrict__ outH,
        __half* __restrict__ outL)
{
    extern __shared__ uint32_t sg[];
    const int bm = blockIdx.y * 128, bn = blockIdx.x * 128;
    const int tid = threadIdx.x, warp = tid >> 5, lane = tid & 31;
    const int wm = (warp & 1) * 64, wn = (warp >> 1) * 32;
    const int grp = lane >> 2, tg = lane & 3;
    const uint32_t sbase = (uint32_t)__cvta_generic_to_shared(sg);

    auto issue = [&](int ks, int stg) {
        const uint32_t base = sbase + (uint32_t)stg*STGW*4;
        const int gw = ks * 16;
        #pragma unroll
        for (int t = 0; t < 6; t++) {
            const int id = tid + t*256;          // 0..1535
            const int plane = id >> 9;
            const int rem = id & 511;
            const int row = rem >> 2, ch = (rem & 3) * 4;
            const uint32_t* src =
                (plane == 0) ? Agh + (((size_t)(bm + row)) << 10) + gw + ch :
                (plane == 1) ? Agl + (((size_t)(bm + row)) << 10) + gw + ch :
                               Wgh + (((size_t)(bn + row)) << 10) + gw + ch;
            cpasync16(base + (uint32_t)(plane*PLANE + row*SROW + ch)*4, src);
        }
    };

    #pragma unroll
    for (int s = 0; s < 3; s++) {
        issue(s, s);
        asm volatile("cp.async.commit_group;\n");
    }

    float acc[4][4][4];
    #pragma unroll
    for (int mi = 0; mi < 4; mi++)
        #pragma unroll
        for (int ni = 0; ni < 4; ni++)
            #pragma unroll
            for (int r = 0; r < 4; r++) acc[mi][ni][r] = 0.f;

    for (int ks = 0; ks < NKCH; ks++) {
        asm volatile("cp.async.wait_group 2;\n");
        __syncthreads();
        const int stg = ks & 3;
        if (ks + 3 < NKCH) issue(ks + 3, (ks + 3) & 3);
        asm volatile("cp.async.commit_group;\n");

        const uint32_t* Ah = sg + stg*STGW;
        const uint32_t* Al = Ah + PLANE;
        const uint32_t* Wh = Ah + 2*PLANE;

        #pragma unroll
        for (int s = 0; s < 2; s++) {
            uint32_t afh[4][4], afl[4][4], bfh[4][2];
            #pragma unroll
            for (int mi = 0; mi < 4; mi++) {
                const int m0 = wm + mi*16 + grp;
                uint2 t0 = *(const uint2*)&Ah[m0*SROW + s*8 + 2*tg];
                uint2 t1 = *(const uint2*)&Ah[(m0+8)*SROW + s*8 + 2*tg];
                afh[mi][0]=t0.x; afh[mi][1]=t1.x; afh[mi][2]=t0.y; afh[mi][3]=t1.y;
                uint2 u0 = *(const uint2*)&Al[m0*SROW + s*8 + 2*tg];
                uint2 u1 = *(const uint2*)&Al[(m0+8)*SROW + s*8 + 2*tg];
                afl[mi][0]=u0.x; afl[mi][1]=u1.x; afl[mi][2]=u0.y; afl[mi][3]=u1.y;
            }
            #pragma unroll
            for (int ni = 0; ni < 4; ni++) {
                uint2 b0 = *(const uint2*)&Wh[(wn + ni*8 + grp)*SROW + s*8 + 2*tg];
                bfh[ni][0] = b0.x; bfh[ni][1] = b0.y;
            }
            #pragma unroll
            for (int mi = 0; mi < 4; mi++)
                #pragma unroll
                for (int ni = 0; ni < 4; ni++) {
                    mma_f16(acc[mi][ni], afh[mi], bfh[ni]);
                    mma_f16(acc[mi][ni], afl[mi], bfh[ni]);
                }
        }
    }

    // epilogue
    float freq[4];
    if (MODE == 1 || MODE == 3) {
        #pragma unroll
        for (int ni = 0; ni < 4; ni++) {
            const int jh = (wn + ni*8 + 2*tg) & 127;
            freq[ni] = (float)exp(-(double)jh * (9.210340371976184 / 128.0));
        }
    }
    #pragma unroll
    for (int mi = 0; mi < 4; mi++) {
        #pragma unroll
        for (int hf = 0; hf < 2; hf++) {
            const int gm = bm + wm + mi*16 + grp + hf*8;
            if (MODE == 2) {
                #pragma unroll
                for (int ni = 0; ni < 4; ni++) {
                    const int col = bn + wn + ni*8 + 2*tg;
                    *(float2*)(outF + (size_t)gm*DMODEL + col)
                        = make_float2(acc[mi][ni][hf*2], acc[mi][ni][hf*2+1]);
                }
            } else {
                const int bb = gm >> 11, ss = gm & (SEQ-1);
                float p = 0.f;
                if (MODE == 1 || MODE == 3) p = (float)pos[gm];
                #pragma unroll
                for (int ni = 0; ni < 4; ni++) {
                    const int col = bn + wn + ni*8 + 2*tg;
                    const int hh = col >> 7, jh = col & 127;
                    float e = acc[mi][ni][hf*2], o = acc[mi][ni][hf*2+1];
                    if (MODE == 1 || MODE == 3) {
                        float sn, cs;
                        sincosf(p * freq[ni], &sn, &cs);
                        const float te = e*cs - o*sn;
                        o = e*sn + o*cs; e = te;
                    }
                    if (MODE == 0) {
                        const int slot = (ss & ~15) + 2*perm8((ss & 15) >> 1) + (ss & 1);
                        __half* vb = outH + ((size_t)(bb*NHEAD + hh)*DKH + jh)*SEQ;
                        vb[slot] = __float2half_rn(e);
                        vb[SEQ + slot] = __float2half_rn(o);
                    } else {
                        const size_t rowq = (size_t)(bb*NHEAD + hh)*SEQ + ss;
                        const int wp = ((jh >> 4) << 3) + perm8((jh & 15) >> 1);
                        const __half he = __float2half_rn(e), ho = __float2half_rn(o);
                        ((uint32_t*)outH)[rowq*64 + wp] = pack2h(he, ho);
                        if (MODE == 1)
                            ((uint32_t*)outL)[rowq*64 + wp]
                                = packh2(e - __half2float(he), o - __half2float(ho));
                    }
                }
            }
        }
    }
}

// ---------------------------------------------------------------------------
// fp16 causal flash attention (R8/R11 fast path), epilogue now writes
// packed hi/lo AO planes (exact split) for the O-projection GEMM.
// ---------------------------------------------------------------------------
#define KB (64*72)
#define VB (128*40)
#define PB (64*40)

__global__ void __launch_bounds__(128)
attn_f16(const uint32_t* __restrict__ Qh, const uint32_t* __restrict__ Ql,
         const uint32_t* __restrict__ Kh, const uint32_t* __restrict__ Vh,
         uint32_t* __restrict__ AOh, uint32_t* __restrict__ AOl)
{
    extern __shared__ uint32_t smw[];
    uint32_t* PSh = smw + 2*KB + 2*VB;
    uint32_t* PSl = PSh + PB;

    const int qt = blockIdx.x, h = blockIdx.y, b = blockIdx.z;
    const int q0 = qt * 64;
    const int tid = threadIdx.x, w = tid >> 5, lane = tid & 31;
    const int grp = lane >> 2, tg = lane & 3;
    const int bh = b*NHEAD + h;
    const uint32_t sbase = (uint32_t)__cvta_generic_to_shared(smw);

    auto issue = [&](int kt, int buf) {
        const uint32_t kd = sbase + (uint32_t)buf*KB*4;
        const uint32_t vd = sbase + (2*KB + (uint32_t)buf*VB)*4;
        const uint32_t* ks = Kh + ((size_t)bh*SEQ + kt*64)*64;
        const uint32_t* vs = Vh + (size_t)bh*DKH*(SEQ/2) + kt*32;
        #pragma unroll
        for (int c = 0; c < 8; c++) {
            const int ch = tid + c*128;
            const int key = ch >> 4, cw = (ch & 15)*4;
            cpasync16(kd + (uint32_t)(key*72 + cw)*4, ks + (size_t)key*64 + cw);
        }
        #pragma unroll
        for (int c = 0; c < 8; c++) {
            const int ch = tid + c*128;
            const int d = ch >> 3, cw = (ch & 7)*4;
            cpasync16(vd + (uint32_t)(d*40 + cw)*4, vs + (size_t)d*(SEQ/2) + cw);
        }
    };

    issue(0, 0);
    asm volatile("cp.async.commit_group;\n");

    const int mlo = q0 + w*16 + grp;
    uint32_t qah[8][4], qal[8][4];
    {
        const uint32_t* qh = Qh + ((size_t)bh*SEQ + mlo)*64;
        const uint32_t* ql = Ql + ((size_t)bh*SEQ + mlo)*64;
        #pragma unroll
        for (int s = 0; s < 8; s++) {
            uint2 t0 = *(const uint2*)&qh[s*8 + 2*tg];
            uint2 t1 = *(const uint2*)&qh[512 + s*8 + 2*tg];
            qah[s][0]=t0.x; qah[s][1]=t1.x; qah[s][2]=t0.y; qah[s][3]=t1.y;
            uint2 u0 = *(const uint2*)&ql[s*8 + 2*tg];
            uint2 u1 = *(const uint2*)&ql[512 + s*8 + 2*tg];
            qal[s][0]=u0.x; qal[s][1]=u1.x; qal[s][2]=u0.y; qal[s][3]=u1.y;
        }
    }

    float oacc[16][4];
    #pragma unroll
    for (int ni = 0; ni < 16; ni++)
        #pragma unroll
        for (int r = 0; r < 4; r++) oacc[ni][r] = 0.f;

    float m_lo = -1e30f, m_hi = -1e30f, l_lo = 0.f, l_hi = 0.f;
    const float scale = 0.08838834764831845f;
    const int prow_lo = (w*16 + grp)*40, prow_hi = prow_lo + 8*40;

    for (int kt = 0; kt <= qt; kt++) {
        const int buf = kt & 1, k0 = kt*64;
        __syncthreads();
        if (kt < qt) {
            issue(kt+1, buf^1);
            asm volatile("cp.async.commit_group;\n");
            asm volatile("cp.async.wait_group 1;\n");
        } else {
            asm volatile("cp.async.wait_group 0;\n");
        }
        __syncthreads();
        const uint32_t* KS = smw + buf*KB;
        const uint32_t* VS = smw + 2*KB + buf*VB;

        float sacc[8][4];
        #pragma unroll
        for (int ni = 0; ni < 8; ni++)
            #pragma unroll
            for (int r = 0; r < 4; r++) sacc[ni][r] = 0.f;
        #pragma unroll
        for (int s = 0; s < 8; s++) {
            #pragma unroll
            for (int ni = 0; ni < 8; ni++) {
                uint2 bk = *(const uint2*)&KS[(ni*8 + grp)*72 + s*8 + 2*tg];
                uint32_t bv[2] = { bk.x, bk.y };
                mma_f16(sacc[ni], qah[s], bv);
                mma_f16(sacc[ni], qal[s], bv);
            }
        }

        const bool diag = (kt == qt);
        float mloc_lo = -1e30f, mloc_hi = -1e30f;
        #pragma unroll
        for (int ni = 0; ni < 8; ni++) {
            const int col = k0 + ni*8 + 2*tg;
            float s0 = sacc[ni][0]*scale, s1 = sacc[ni][1]*scale;
            float s2 = sacc[ni][2]*scale, s3 = sacc[ni][3]*scale;
            if (diag) {
                if (col     > mlo    ) s0 = -1e30f;
                if (col + 1 > mlo    ) s1 = -1e30f;
                if (col     > mlo + 8) s2 = -1e30f;
                if (col + 1 > mlo + 8) s3 = -1e30f;
            }
            sacc[ni][0]=s0; sacc[ni][1]=s1; sacc[ni][2]=s2; sacc[ni][3]=s3;
            mloc_lo = fmaxf(mloc_lo, fmaxf(s0, s1));
            mloc_hi = fmaxf(mloc_hi, fmaxf(s2, s3));
        }
        mloc_lo = fmaxf(mloc_lo, __shfl_xor_sync(0xffffffffu, mloc_lo, 1));
        mloc_lo = fmaxf(mloc_lo, __shfl_xor_sync(0xffffffffu, mloc_lo, 2));
        mloc_hi = fmaxf(mloc_hi, __shfl_xor_sync(0xffffffffu, mloc_hi, 1));
        mloc_hi = fmaxf(mloc_hi, __shfl_xor_sync(0xffffffffu, mloc_hi, 2));
        const float mn_lo = fmaxf(m_lo, mloc_lo), mn_hi = fmaxf(m_hi, mloc_hi);
        const float corr_lo = __expf(m_lo - mn_lo), corr_hi = __expf(m_hi - mn_hi);

        float ls_lo = 0.f, ls_hi = 0.f;
        #pragma unroll
        for (int ni = 0; ni < 8; ni++) {
            const float p0 = __expf(sacc[ni][0] - mn_lo);
            const float p1 = __expf(sacc[ni][1] - mn_lo);
            const float p2 = __expf(sacc[ni][2] - mn_hi);
            const float p3 = __expf(sacc[ni][3] - mn_hi);
            ls_lo += p0 + p1;  ls_hi += p2 + p3;
            const int kwi = ni*4 + tg;
            const int pp = ((kwi >> 3) << 3) + perm8(kwi & 7);
            uint32_t hi, lo;
            split2(p0, p1, hi, lo);
            PSh[prow_lo + pp] = hi;  PSl[prow_lo + pp] = lo;
            split2(p2, p3, hi, lo);
            PSh[prow_hi + pp] = hi;  PSl[prow_hi + pp] = lo;
        }
        l_lo = l_lo*corr_lo + ls_lo;  m_lo = mn_lo;
        l_hi = l_hi*corr_hi + ls_hi;  m_hi = mn_hi;
        #pragma unroll
        for (int ni = 0; ni < 16; ni++) {
            oacc[ni][0] *= corr_lo; oacc[ni][1] *= corr_lo;
            oacc[ni][2] *= corr_hi; oacc[ni][3] *= corr_hi;
        }
        __syncwarp();

        #pragma unroll
        for (int kk = 0; kk < 4; kk++) {
            uint2 plh = *(const uint2*)&PSh[prow_lo + kk*8 + 2*tg];
            uint2 phh = *(const uint2*)&PSh[prow_hi + kk*8 + 2*tg];
            uint32_t pah[4] = { plh.x, phh.x, plh.y, phh.y };
            uint2 pll = *(const uint2*)&PSl[prow_lo + kk*8 + 2*tg];
            uint2 phl = *(const uint2*)&PSl[prow_hi + kk*8 + 2*tg];
            uint32_t pal[4] = { pll.x, phl.x, pll.y, phl.y };
            #pragma unroll
            for (int ni = 0; ni < 16; ni++) {
                uint2 bv2 = *(const uint2*)&VS[(ni*8 + grp)*40 + kk*8 + 2*tg];
                uint32_t bv[2] = { bv2.x, bv2.y };
                mma_f16(oacc[ni], pah, bv);
                mma_f16(oacc[ni], pal, bv);
            }
        }
    }

    // epilogue: normalize, exact hi/lo split, write packed AO planes
    l_lo += __shfl_xor_sync(0xffffffffu, l_lo, 1);
    l_lo += __shfl_xor_sync(0xffffffffu, l_lo, 2);
    l_hi += __shfl_xor_sync(0xffffffffu, l_hi, 1);
    l_hi += __shfl_xor_sync(0xffffffffu, l_hi, 2);
    const float iv_lo = 1.f / l_lo, iv_hi = 1.f / l_hi;
    const int row_lo = b*SEQ + mlo;
    #pragma unroll
    for (int ni = 0; ni < 16; ni++) {
        const int c = h*DKH + ni*8 + 2*tg;
        const int cpair = c >> 1;
        const int wp = ((cpair >> 3) << 3) + perm8(cpair & 7);
        uint32_t hi, lo;
        split2(oacc[ni][0]*iv_lo, oacc[ni][1]*iv_lo, hi, lo);
        AOh[((size_t)row_lo << 10) + wp] = hi;
        AOl[((size_t)row_lo << 10) + wp] = lo;
        split2(oacc[ni][2]*iv_hi, oacc[ni][3]*iv_hi, hi, lo);
        AOh[((size_t)(row_lo + 8) << 10) + wp] = hi;
        AOl[((size_t)(row_lo + 8) << 10) + wp] = lo;
    }
}

// ---------------------------------------------------------------------------
extern "C" void kernel_launch(void* const* d_in, const int* in_sizes, int n_in,
                              void* d_out, int out_size)
{
    (void)in_sizes; (void)n_in; (void)out_size;
    const float* x  = (const float*)d_in[0];
    const int*   tp = (const int*)  d_in[1];
    const float* wq = (const float*)d_in[2];
    const float* wk = (const float*)d_in[3];
    const float* wv = (const float*)d_in[4];
    const float* wo = (const float*)d_in[5];
    float* out = (float*)d_out;

    uint32_t *Xh, *Xl, *Wq, *Wk, *Wv, *Wo, *AOh, *AOl;
    __half *Qh, *Ql, *Kh, *Vh;
    cudaGetSymbolAddress((void**)&Xh,  g_Xh);
    cudaGetSymbolAddress((void**)&Xl,  g_Xl);
    cudaGetSymbolAddress((void**)&Wq,  g_Wq);
    cudaGetSymbolAddress((void**)&Wk,  g_Wk);
    cudaGetSymbolAddress((void**)&Wv,  g_Wv);
    cudaGetSymbolAddress((void**)&Wo,  g_Wo);
    cudaGetSymbolAddress((void**)&AOh, g_AOh);
    cudaGetSymbolAddress((void**)&AOl, g_AOl);
    cudaGetSymbolAddress((void**)&Qh,  g_Qh);
    cudaGetSymbolAddress((void**)&Ql,  g_Ql);
    cudaGetSymbolAddress((void**)&Kh,  g_Kh);
    cudaGetSymbolAddress((void**)&Vh,  g_Vh);

    // prep: pack x (hi+lo) and weights (hi)
    const int xw = MTOT*RW, ww = DMODEL*RW;
    pack_rows<<<(xw + 255)/256, 256>>>(x,  Xh, Xl, xw);
    pack_rows<<<(ww + 255)/256, 256>>>(wq, Wq, nullptr, ww);
    pack_rows<<<(ww + 255)/256, 256>>>(wk, Wk, nullptr, ww);
    pack_rows<<<(ww + 255)/256, 256>>>(wv, Wv, nullptr, ww);
    pack_rows<<<(ww + 255)/256, 256>>>(wo, Wo, nullptr, ww);

    const int gsm = 4*STGW*4;
    cudaFuncSetAttribute(gemm_pk<0>, cudaFuncAttributeMaxDynamicSharedMemorySize, gsm);
    cudaFuncSetAttribute(gemm_pk<1>, cudaFuncAttributeMaxDynamicSharedMemorySize, gsm);
    cudaFuncSetAttribute(gemm_pk<2>, cudaFuncAttributeMaxDynamicSharedMemorySize, gsm);
    cudaFuncSetAttribute(gemm_pk<3>, cudaFuncAttributeMaxDynamicSharedMemorySize, gsm);

    const dim3 gg(DMODEL/128, MTOT/128);
    gemm_pk<1><<<gg, 256, gsm>>>(Xh, Xl, Wq, tp, nullptr, Qh, Ql);
    gemm_pk<3><<<gg, 256, gsm>>>(Xh, Xl, Wk, tp, nullptr, Kh, nullptr);
    gemm_pk<0><<<gg, 256, gsm>>>(Xh, Xl, Wv, tp, nullptr, Vh, nullptr);

    const int asm_bytes = (2*KB + 2*VB + 2*PB) * 4;
    cudaFuncSetAttribute(attn_f16, cudaFuncAttributeMaxDynamicSharedMemorySize, asm_bytes);
    attn_f16<<<dim3(SEQ/64, NHEAD, BATCH), 128, asm_bytes>>>(
        (const uint32_t*)Qh, (const uint32_t*)Ql,
        (const uint32_t*)Kh, (const uint32_t*)Vh, AOh, AOl);

    gemm_pk<2><<<gg, 256, gsm>>>(AOh, AOl, Wo, tp, out, nullptr, nullptr);
}

// round 15
// speedup vs baseline: 1.8602x; 1.7733x over previous
#include <cuda_runtime.h>
#include <cuda_fp16.h>
#include <math.h>
#include <stdint.h>

#define BATCH  2
#define SEQ    2048
#define DMODEL 2048
#define NHEAD  16
#define DKH    128
#define MTOT   (BATCH*SEQ)
#define RW     (DMODEL/2)   // 1024 words per packed row

// Packed planes: rows of 1024 uint32 words, fragment-permuted fp16 pairs.
__device__ uint32_t g_Xh[(size_t)MTOT*RW];
__device__ uint32_t g_Wq[(size_t)DMODEL*RW];
__device__ uint32_t g_Wk[(size_t)DMODEL*RW];
__device__ uint32_t g_Wv[(size_t)DMODEL*RW];
__device__ uint32_t g_Wo[(size_t)DMODEL*RW];
__device__ uint32_t g_AOh[(size_t)MTOT*RW];
// Attention operand layouts.
__device__ __half g_Qh[(size_t)BATCH*NHEAD*SEQ*DKH];
__device__ __half g_Kh[(size_t)BATCH*NHEAD*SEQ*DKH];
__device__ __half g_Vh[(size_t)BATCH*NHEAD*DKH*SEQ];

__device__ __forceinline__ int perm8(int r) { return ((r & 3) << 1) | (r >> 2); }
__device__ __forceinline__ uint32_t packh2(float a, float b) {
    __half2 h = __floats2half2_rn(a, b);
    return *reinterpret_cast<uint32_t*>(&h);
}
__device__ __forceinline__ void mma_f16(float* d, const uint32_t* a, const uint32_t* b) {
    asm volatile(
        "mma.sync.aligned.m16n8k16.row.col.f32.f16.f16.f32 "
        "{%0,%1,%2,%3}, {%4,%5,%6,%7}, {%8,%9}, {%0,%1,%2,%3};\n"
        : "+f"(d[0]), "+f"(d[1]), "+f"(d[2]), "+f"(d[3])
        : "r"(a[0]), "r"(a[1]), "r"(a[2]), "r"(a[3]), "r"(b[0]), "r"(b[1]));
}
__device__ __forceinline__ void cpasync16(uint32_t s, const void* g) {
    asm volatile("cp.async.cg.shared.global [%0], [%1], 16;\n" :: "r"(s), "l"(g));
}

// ---------------------------------------------------------------------------
// Prep: fp32 rows -> packed fp16 plane in fragment-word layout.
// ---------------------------------------------------------------------------
__global__ void __launch_bounds__(256)
pack_rows(const float* __restrict__ src, uint32_t* __restrict__ hi, int nwords)
{
    const int idx = blockIdx.x * 256 + threadIdx.x;
    if (idx >= nwords) return;
    const int cpair = idx & (RW-1), row = idx >> 10;
    const int wp = ((cpair >> 3) << 3) + perm8(cpair & 7);
    const float2 v = ((const float2*)src)[idx];
    hi[((size_t)row << 10) + wp] = packh2(v.x, v.y);
}

// ---------------------------------------------------------------------------
// Packed single-term fp16 GEMM: C = A x W^T (both operands rounded once).
// 4-stage cp.async pipeline, zero in-loop conversion, 1 barrier per chunk.
// MODE 1: Q/K out (RoPE, head layout)  MODE 0: V out (transposed)
// MODE 2: fp32 out (O-projection)
// ---------------------------------------------------------------------------
#define SROW  24
#define PLANE (128*SROW)
#define STGW  (2*PLANE)
#define NKCH  (DMODEL/32)

template<int MODE>
__global__ void __launch_bounds__(256, 2)
gemm_pk(const uint32_t* __restrict__ Agh, const uint32_t* __restrict__ Wgh,
        const int* __restrict__ pos, float* __restrict__ outF,
        __half* __restrict__ outH)
{
    extern __shared__ uint32_t sg[];
    const int bm = blockIdx.y * 128, bn = blockIdx.x * 128;
    const int tid = threadIdx.x, warp = tid >> 5, lane = tid & 31;
    const int wm = (warp & 1) * 64, wn = (warp >> 1) * 32;
    const int grp = lane >> 2, tg = lane & 3;
    const uint32_t sbase = (uint32_t)__cvta_generic_to_shared(sg);

    auto issue = [&](int ks, int stg) {
        const uint32_t base = sbase + (uint32_t)stg*STGW*4;
        const int gw = ks * 16;
        #pragma unroll
        for (int t = 0; t < 4; t++) {
            const int id = tid + t*256;          // 0..1023
            const int plane = id >> 9;
            const int rem = id & 511;
            const int row = rem >> 2, ch = (rem & 3) * 4;
            const uint32_t* src =
                (plane == 0) ? Agh + (((size_t)(bm + row)) << 10) + gw + ch :
                               Wgh + (((size_t)(bn + row)) << 10) + gw + ch;
            cpasync16(base + (uint32_t)(plane*PLANE + row*SROW + ch)*4, src);
        }
    };

    #pragma unroll
    for (int s = 0; s < 3; s++) {
        issue(s, s);
        asm volatile("cp.async.commit_group;\n");
    }

    float acc[4][4][4];
    #pragma unroll
    for (int mi = 0; mi < 4; mi++)
        #pragma unroll
        for (int ni = 0; ni < 4; ni++)
            #pragma unroll
            for (int r = 0; r < 4; r++) acc[mi][ni][r] = 0.f;

    for (int ks = 0; ks < NKCH; ks++) {
        asm volatile("cp.async.wait_group 2;\n");
        __syncthreads();
        const int stg = ks & 3;
        if (ks + 3 < NKCH) issue(ks + 3, (ks + 3) & 3);
        asm volatile("cp.async.commit_group;\n");

        const uint32_t* Ah = sg + stg*STGW;
        const uint32_t* Wh = Ah + PLANE;

        #pragma unroll
        for (int s = 0; s < 2; s++) {
            uint32_t afh[4][4], bfh[4][2];
            #pragma unroll
            for (int mi = 0; mi < 4; mi++) {
                const int m0 = wm + mi*16 + grp;
                uint2 t0 = *(const uint2*)&Ah[m0*SROW + s*8 + 2*tg];
                uint2 t1 = *(const uint2*)&Ah[(m0+8)*SROW + s*8 + 2*tg];
                afh[mi][0]=t0.x; afh[mi][1]=t1.x; afh[mi][2]=t0.y; afh[mi][3]=t1.y;
            }
            #pragma unroll
            for (int ni = 0; ni < 4; ni++) {
                uint2 b0 = *(const uint2*)&Wh[(wn + ni*8 + grp)*SROW + s*8 + 2*tg];
                bfh[ni][0] = b0.x; bfh[ni][1] = b0.y;
            }
            #pragma unroll
            for (int mi = 0; mi < 4; mi++)
                #pragma unroll
                for (int ni = 0; ni < 4; ni++)
                    mma_f16(acc[mi][ni], afh[mi], bfh[ni]);
        }
    }

    // epilogue
    float freq[4];
    if (MODE == 1) {
        #pragma unroll
        for (int ni = 0; ni < 4; ni++) {
            const int jh = (wn + ni*8 + 2*tg) & 127;
            freq[ni] = (float)exp(-(double)jh * (9.210340371976184 / 128.0));
        }
    }
    #pragma unroll
    for (int mi = 0; mi < 4; mi++) {
        #pragma unroll
        for (int hf = 0; hf < 2; hf++) {
            const int gm = bm + wm + mi*16 + grp + hf*8;
            if (MODE == 2) {
                #pragma unroll
                for (int ni = 0; ni < 4; ni++) {
                    const int col = bn + wn + ni*8 + 2*tg;
                    *(float2*)(outF + (size_t)gm*DMODEL + col)
                        = make_float2(acc[mi][ni][hf*2], acc[mi][ni][hf*2+1]);
                }
            } else {
                const int bb = gm >> 11, ss = gm & (SEQ-1);
                float p = 0.f;
                if (MODE == 1) p = (float)pos[gm];
                #pragma unroll
                for (int ni = 0; ni < 4; ni++) {
                    const int col = bn + wn + ni*8 + 2*tg;
                    const int hh = col >> 7, jh = col & 127;
                    float e = acc[mi][ni][hf*2], o = acc[mi][ni][hf*2+1];
                    if (MODE == 1) {
                        float sn, cs;
                        sincosf(p * freq[ni], &sn, &cs);
                        const float te = e*cs - o*sn;
                        o = e*sn + o*cs; e = te;
                    }
                    if (MODE == 0) {
                        const int slot = (ss & ~15) + 2*perm8((ss & 15) >> 1) + (ss & 1);
                        __half* vb = outH + ((size_t)(bb*NHEAD + hh)*DKH + jh)*SEQ;
                        vb[slot] = __float2half_rn(e);
                        vb[SEQ + slot] = __float2half_rn(o);
                    } else {
                        const size_t rowq = (size_t)(bb*NHEAD + hh)*SEQ + ss;
                        const int wp = ((jh >> 4) << 3) + perm8((jh & 15) >> 1);
                        ((uint32_t*)outH)[rowq*64 + wp] = packh2(e, o);
                    }
                }
            }
        }
    }
}

// ---------------------------------------------------------------------------
// fp16 causal flash attention, single-term (Q, K, V, P all rounded once).
// cp.async double-buffered K/V tiles (pre-permuted word layouts).
// ---------------------------------------------------------------------------
#define KB (64*72)
#define VB (128*40)
#define PB (64*40)

__global__ void __launch_bounds__(128)
attn_f16(const uint32_t* __restrict__ Qh, const uint32_t* __restrict__ Kh,
         const uint32_t* __restrict__ Vh, uint32_t* __restrict__ AOh)
{
    extern __shared__ uint32_t smw[];
    uint32_t* PSh = smw + 2*KB + 2*VB;

    const int qt = blockIdx.x, h = blockIdx.y, b = blockIdx.z;
    const int q0 = qt * 64;
    const int tid = threadIdx.x, w = tid >> 5, lane = tid & 31;
    const int grp = lane >> 2, tg = lane & 3;
    const int bh = b*NHEAD + h;
    const uint32_t sbase = (uint32_t)__cvta_generic_to_shared(smw);

    auto issue = [&](int kt, int buf) {
        const uint32_t kd = sbase + (uint32_t)buf*KB*4;
        const uint32_t vd = sbase + (2*KB + (uint32_t)buf*VB)*4;
        const uint32_t* ks = Kh + ((size_t)bh*SEQ + kt*64)*64;
        const uint32_t* vs = Vh + (size_t)bh*DKH*(SEQ/2) + kt*32;
        #pragma unroll
        for (int c = 0; c < 8; c++) {
            const int ch = tid + c*128;
            const int key = ch >> 4, cw = (ch & 15)*4;
            cpasync16(kd + (uint32_t)(key*72 + cw)*4, ks + (size_t)key*64 + cw);
        }
        #pragma unroll
        for (int c = 0; c < 8; c++) {
            const int ch = tid + c*128;
            const int d = ch >> 3, cw = (ch & 7)*4;
            cpasync16(vd + (uint32_t)(d*40 + cw)*4, vs + (size_t)d*(SEQ/2) + cw);
        }
    };

    issue(0, 0);
    asm volatile("cp.async.commit_group;\n");

    // Q fragments, LDG overlapped with tile-0 copy
    const int mlo = q0 + w*16 + grp;
    uint32_t qah[8][4];
    {
        const uint32_t* qh = Qh + ((size_t)bh*SEQ + mlo)*64;
        #pragma unroll
        for (int s = 0; s < 8; s++) {
            uint2 t0 = *(const uint2*)&qh[s*8 + 2*tg];
            uint2 t1 = *(const uint2*)&qh[512 + s*8 + 2*tg];
            qah[s][0]=t0.x; qah[s][1]=t1.x; qah[s][2]=t0.y; qah[s][3]=t1.y;
        }
    }

    float oacc[16][4];
    #pragma unroll
    for (int ni = 0; ni < 16; ni++)
        #pragma unroll
        for (int r = 0; r < 4; r++) oacc[ni][r] = 0.f;

    float m_lo = -1e30f, m_hi = -1e30f, l_lo = 0.f, l_hi = 0.f;
    const float scale = 0.08838834764831845f;
    const int prow_lo = (w*16 + grp)*40, prow_hi = prow_lo + 8*40;

    for (int kt = 0; kt <= qt; kt++) {
        const int buf = kt & 1, k0 = kt*64;
        __syncthreads();
        if (kt < qt) {
            issue(kt+1, buf^1);
            asm volatile("cp.async.commit_group;\n");
            asm volatile("cp.async.wait_group 1;\n");
        } else {
            asm volatile("cp.async.wait_group 0;\n");
        }
        __syncthreads();
        const uint32_t* KS = smw + buf*KB;
        const uint32_t* VS = smw + 2*KB + buf*VB;

        // S = Q K^T
        float sacc[8][4];
        #pragma unroll
        for (int ni = 0; ni < 8; ni++)
            #pragma unroll
            for (int r = 0; r < 4; r++) sacc[ni][r] = 0.f;
        #pragma unroll
        for (int s = 0; s < 8; s++) {
            #pragma unroll
            for (int ni = 0; ni < 8; ni++) {
                uint2 bk = *(const uint2*)&KS[(ni*8 + grp)*72 + s*8 + 2*tg];
                uint32_t bv[2] = { bk.x, bk.y };
                mma_f16(sacc[ni], qah[s], bv);
            }
        }

        // online softmax (fp32)
        const bool diag = (kt == qt);
        float mloc_lo = -1e30f, mloc_hi = -1e30f;
        #pragma unroll
        for (int ni = 0; ni < 8; ni++) {
            const int col = k0 + ni*8 + 2*tg;
            float s0 = sacc[ni][0]*scale, s1 = sacc[ni][1]*scale;
            float s2 = sacc[ni][2]*scale, s3 = sacc[ni][3]*scale;
            if (diag) {
                if (col     > mlo    ) s0 = -1e30f;
                if (col + 1 > mlo    ) s1 = -1e30f;
                if (col     > mlo + 8) s2 = -1e30f;
                if (col + 1 > mlo + 8) s3 = -1e30f;
            }
            sacc[ni][0]=s0; sacc[ni][1]=s1; sacc[ni][2]=s2; sacc[ni][3]=s3;
            mloc_lo = fmaxf(mloc_lo, fmaxf(s0, s1));
            mloc_hi = fmaxf(mloc_hi, fmaxf(s2, s3));
        }
        mloc_lo = fmaxf(mloc_lo, __shfl_xor_sync(0xffffffffu, mloc_lo, 1));
        mloc_lo = fmaxf(mloc_lo, __shfl_xor_sync(0xffffffffu, mloc_lo, 2));
        mloc_hi = fmaxf(mloc_hi, __shfl_xor_sync(0xffffffffu, mloc_hi, 1));
        mloc_hi = fmaxf(mloc_hi, __shfl_xor_sync(0xffffffffu, mloc_hi, 2));
        const float mn_lo = fmaxf(m_lo, mloc_lo), mn_hi = fmaxf(m_hi, mloc_hi);
        const float corr_lo = __expf(m_lo - mn_lo), corr_hi = __expf(m_hi - mn_hi);

        float ls_lo = 0.f, ls_hi = 0.f;
        #pragma unroll
        for (int ni = 0; ni < 8; ni++) {
            const float p0 = __expf(sacc[ni][0] - mn_lo);
            const float p1 = __expf(sacc[ni][1] - mn_lo);
            const float p2 = __expf(sacc[ni][2] - mn_hi);
            const float p3 = __expf(sacc[ni][3] - mn_hi);
            ls_lo += p0 + p1;  ls_hi += p2 + p3;
            const int kwi = ni*4 + tg;
            const int pp = ((kwi >> 3) << 3) + perm8(kwi & 7);
            PSh[prow_lo + pp] = packh2(p0, p1);
            PSh[prow_hi + pp] = packh2(p2, p3);
        }
        l_lo = l_lo*corr_lo + ls_lo;  m_lo = mn_lo;
        l_hi = l_hi*corr_hi + ls_hi;  m_hi = mn_hi;
        #pragma unroll
        for (int ni = 0; ni < 16; ni++) {
            oacc[ni][0] *= corr_lo; oacc[ni][1] *= corr_lo;
            oacc[ni][2] *= corr_hi; oacc[ni][3] *= corr_hi;
        }
        __syncwarp();

        // O += P V
        #pragma unroll
        for (int kk = 0; kk < 4; kk++) {
            uint2 plh = *(const uint2*)&PSh[prow_lo + kk*8 + 2*tg];
            uint2 phh = *(const uint2*)&PSh[prow_hi + kk*8 + 2*tg];
            uint32_t pah[4] = { plh.x, phh.x, plh.y, phh.y };
            #pragma unroll
            for (int ni = 0; ni < 16; ni++) {
                uint2 bv2 = *(const uint2*)&VS[(ni*8 + grp)*40 + kk*8 + 2*tg];
                uint32_t bv[2] = { bv2.x, bv2.y };
                mma_f16(oacc[ni], pah, bv);
            }
        }
    }

    // epilogue: normalize, round once, write packed AO plane
    l_lo += __shfl_xor_sync(0xffffffffu, l_lo, 1);
    l_lo += __shfl_xor_sync(0xffffffffu, l_lo, 2);
    l_hi += __shfl_xor_sync(0xffffffffu, l_hi, 1);
    l_hi += __shfl_xor_sync(0xffffffffu, l_hi, 2);
    const float iv_lo = 1.f / l_lo, iv_hi = 1.f / l_hi;
    const int row_lo = b*SEQ + mlo;
    #pragma unroll
    for (int ni = 0; ni < 16; ni++) {
        const int c = h*DKH + ni*8 + 2*tg;
        const int cpair = c >> 1;
        const int wp = ((cpair >> 3) << 3) + perm8(cpair & 7);
        AOh[((size_t)row_lo << 10) + wp]
            = packh2(oacc[ni][0]*iv_lo, oacc[ni][1]*iv_lo);
        AOh[((size_t)(row_lo + 8) << 10) + wp]
            = packh2(oacc[ni][2]*iv_hi, oacc[ni][3]*iv_hi);
    }
}

// ---------------------------------------------------------------------------
extern "C" void kernel_launch(void* const* d_in, const int* in_sizes, int n_in,
                              void* d_out, int out_size)
{
    (void)in_sizes; (void)n_in; (void)out_size;
    const float* x  = (const float*)d_in[0];
    const int*   tp = (const int*)  d_in[1];
    const float* wq = (const float*)d_in[2];
    const float* wk = (const float*)d_in[3];
    const float* wv = (const float*)d_in[4];
    const float* wo = (const float*)d_in[5];
    float* out = (float*)d_out;

    uint32_t *Xh, *Wq, *Wk, *Wv, *Wo, *AOh;
    __half *Qh, *Kh, *Vh;
    cudaGetSymbolAddress((void**)&Xh,  g_Xh);
    cudaGetSymbolAddress((void**)&Wq,  g_Wq);
    cudaGetSymbolAddress((void**)&Wk,  g_Wk);
    cudaGetSymbolAddress((void**)&Wv,  g_Wv);
    cudaGetSymbolAddress((void**)&Wo,  g_Wo);
    cudaGetSymbolAddress((void**)&AOh, g_AOh);
    cudaGetSymbolAddress((void**)&Qh,  g_Qh);
    cudaGetSymbolAddress((void**)&Kh,  g_Kh);
    cudaGetSymbolAddress((void**)&Vh,  g_Vh);

    // prep: pack x and weights (hi planes only)
    const int xw = MTOT*RW, ww = DMODEL*RW;
    pack_rows<<<(xw + 255)/256, 256>>>(x,  Xh, xw);
    pack_rows<<<(ww + 255)/256, 256>>>(wq, Wq, ww);
    pack_rows<<<(ww + 255)/256, 256>>>(wk, Wk, ww);
    pack_rows<<<(ww + 255)/256, 256>>>(wv, Wv, ww);
    pack_rows<<<(ww + 255)/256, 256>>>(wo, Wo, ww);

    const int gsm = 4*STGW*4;
    cudaFuncSetAttribute(gemm_pk<0>, cudaFuncAttributeMaxDynamicSharedMemorySize, gsm);
    cudaFuncSetAttribute(gemm_pk<1>, cudaFuncAttributeMaxDynamicSharedMemorySize, gsm);
    cudaFuncSetAttribute(gemm_pk<2>, cudaFuncAttributeMaxDynamicSharedMemorySize, gsm);

    const dim3 gg(DMODEL/128, MTOT/128);
    gemm_pk<1><<<gg, 256, gsm>>>(Xh, Wq, tp, nullptr, Qh);
    gemm_pk<1><<<gg, 256, gsm>>>(Xh, Wk, tp, nullptr, Kh);
    gemm_pk<0><<<gg, 256, gsm>>>(Xh, Wv, tp, nullptr, Vh);

    const int asm_bytes = (2*KB + 2*VB + PB) * 4;
    cudaFuncSetAttribute(attn_f16, cudaFuncAttributeMaxDynamicSharedMemorySize, asm_bytes);
    attn_f16<<<dim3(SEQ/64, NHEAD, BATCH), 128, asm_bytes>>>(
        (const uint32_t*)Qh, (const uint32_t*)Kh, (const uint32_t*)Vh, AOh);

    gemm_pk<2><<<gg, 256, gsm>>>(AOh, Wo, tp, out, nullptr);
}